// round 9
// baseline (speedup 1.0000x reference)
#include <cuda_runtime.h>
#include <cuda_bf16.h>
#include <cstdint>

// ---------------- problem constants ----------------
#define N_ROWS   65536
#define K_CODES  1024
#define D_DIM    64
#define M_TILE   128                    // rows per CTA
#define THREADS  256
#define NUM_BLOCKS (N_ROWS / M_TILE)    // 512
#define N_MB     (N_ROWS / 16)          // 4096 A row-blocks
#define N_NB     (K_CODES / 8)          // 128 B code-blocks
#define CAP      64
#define MARGIN   0.0625f

// Output layout (floats): [quantized 4194304][loss 1][indices 65536]
#define OUT_LOSS (N_ROWS * D_DIM)
#define OUT_IDX  (OUT_LOSS + 1)

// ---------------- device globals ----------------
// A fragments: [mb][kb][lane][reg] u32 (2 bf16 each), mma m16n8k16 order
__device__ uint32_t g_Ah[N_MB * 4 * 32 * 4];   // 8 MB
__device__ uint32_t g_Am[N_MB * 4 * 32 * 4];   // 8 MB
// B fragments: [nb][kb][lane][reg(2)] u32
__device__ uint32_t g_Bh[N_NB * 4 * 32 * 2];   // 128 KB
__device__ uint32_t g_Bm[N_NB * 4 * 32 * 2];   // 128 KB
__device__ float g_normE[K_CODES];
__device__ float g_partials[NUM_BLOCKS];

// ---------------- smem layout (bytes) ----------------
#define SM_B     0        // 65536: [plane(2)][nbl(32)][kb(4)][lane(32)][reg(2)] u32
#define SM_NORM  65536    // 4096: 1024 floats
#define SM_CANDI 69632    // 16384: 128 * CAP u16
#define SM_CNT   86016    // 512: 128 ints
#define SM_TOTAL 86528

// ---------------- helpers ----------------
__device__ __forceinline__ uint32_t pack_bf16(float lo, float hi) {
    __nv_bfloat16 a = __float2bfloat16(lo);
    __nv_bfloat16 b = __float2bfloat16(hi);
    uint16_t ua = *(uint16_t*)&a, ub = *(uint16_t*)&b;
    return (uint32_t)ua | ((uint32_t)ub << 16);
}
__device__ __forceinline__ float bf16val(float v) {
    __nv_bfloat16 b = __float2bfloat16(v);
    return __bfloat162float(b);
}
__device__ __forceinline__ void mma_bf16(float* c, const uint32_t* a,
                                         uint32_t b0, uint32_t b1) {
    asm volatile(
        "mma.sync.aligned.m16n8k16.row.col.f32.bf16.bf16.f32 "
        "{%0,%1,%2,%3}, {%4,%5,%6,%7}, {%8,%9}, {%0,%1,%2,%3};"
        : "+f"(c[0]), "+f"(c[1]), "+f"(c[2]), "+f"(c[3])
        : "r"(a[0]), "r"(a[1]), "r"(a[2]), "r"(a[3]), "r"(b0), "r"(b1));
}

// ---------------------------------------------------------------------------
// Prep A: split (-2*X) into (hi, mid) bf16 planes, mma-fragment order
// ---------------------------------------------------------------------------
__global__ void vq_prepA(const float* __restrict__ X) {
    int tid = blockIdx.x * blockDim.x + threadIdx.x;
    if (tid >= N_MB * 4 * 32 * 4) return;
    int reg = tid & 3, lane = (tid >> 2) & 31, kb = (tid >> 7) & 3, mb = tid >> 9;
    int g = lane >> 2, tg = lane & 3;
    int row = mb * 16 + g + ((reg & 1) << 3);
    int col = kb * 16 + tg * 2 + ((reg & 2) << 2);
    const float* xp = X + (size_t)row * D_DIM + col;
    float v0 = -2.0f * xp[0], v1 = -2.0f * xp[1];
    float h0 = bf16val(v0), h1 = bf16val(v1);
    g_Ah[tid] = pack_bf16(v0, v1);
    g_Am[tid] = pack_bf16(v0 - h0, v1 - h1);
}

// ---------------------------------------------------------------------------
// Prep B: split E into (hi, mid) bf16 planes, mma-fragment order
// ---------------------------------------------------------------------------
__global__ void vq_prepB(const float* __restrict__ E) {
    int tid = blockIdx.x * blockDim.x + threadIdx.x;
    if (tid >= N_NB * 4 * 32 * 2) return;
    int reg = tid & 1, lane = (tid >> 1) & 31, kb = (tid >> 6) & 3, nb = tid >> 8;
    int g = lane >> 2, tg = lane & 3;
    int code = nb * 8 + g;
    int k = kb * 16 + tg * 2 + reg * 8;
    const float* ep = E + (size_t)code * D_DIM + k;
    float v0 = ep[0], v1 = ep[1];
    float h0 = bf16val(v0), h1 = bf16val(v1);
    g_Bh[tid] = pack_bf16(v0, v1);
    g_Bm[tid] = pack_bf16(v0 - h0, v1 - h1);
}

// ---------------------------------------------------------------------------
// Codebook norms
// ---------------------------------------------------------------------------
__global__ void vq_norm_kernel(const float* __restrict__ E) {
    int k = blockIdx.x * blockDim.x + threadIdx.x;
    if (k < K_CODES) {
        const float4* e = (const float4*)(E + (size_t)k * D_DIM);
        float s = 0.f;
#pragma unroll
        for (int i = 0; i < D_DIM / 4; ++i) {
            float4 v = e[i];
            s += v.x * v.x + v.y * v.y + v.z * v.z + v.w * v.w;
        }
        g_normE[k] = s;
    }
}

// ---------------------------------------------------------------------------
// Main: HMMA split distance GEMM (3 independent accumulator chains,
//       natural register allocation — NO minBlocks reg cap)
//       + margin-candidate argmin (index-only list) + exact fp32 refine
// ---------------------------------------------------------------------------
__global__ __launch_bounds__(THREADS) void vq_main_kernel(
    const float* __restrict__ X, const float* __restrict__ E,
    float* __restrict__ out)
{
    extern __shared__ char smem[];
    float* snorm = (float*)(smem + SM_NORM);
    unsigned short* candI = (unsigned short*)(smem + SM_CANDI);
    int* cnt = (int*)(smem + SM_CNT);

    const int t = threadIdx.x;
    const int w = t >> 5, l = t & 31;
    const int g = l >> 2, tg = l & 3;
    const int rowBase = blockIdx.x * M_TILE;

    if (t < M_TILE) cnt[t] = 0;
    for (int i = t; i < K_CODES; i += THREADS) snorm[i] = g_normE[i];

    // A fragments in registers for this warp's 16 rows
    const int mb = blockIdx.x * 8 + w;
    uint4 aH[4], aM[4];
#pragma unroll
    for (int kb = 0; kb < 4; ++kb) {
        aH[kb] = *(const uint4*)&g_Ah[((mb * 4 + kb) * 32 + l) * 4];
        aM[kb] = *(const uint4*)&g_Am[((mb * 4 + kb) * 32 + l) * 4];
    }

    float minv0 = 3.4e38f, minv1 = 3.4e38f;
    const int rL0 = w * 16 + g, rL1 = rL0 + 8;

#pragma unroll 1
    for (int tile = 0; tile < 4; ++tile) {
        __syncthreads();
        // stage B tile (32 nblocks, both planes) = 64KB
        {
            const uint4* srcH = (const uint4*)(g_Bh + tile * 8192);
            const uint4* srcM = (const uint4*)(g_Bm + tile * 8192);
            uint4* dst = (uint4*)(smem + SM_B);
#pragma unroll
            for (int i = 0; i < 16; ++i) {
                int idx = t + i * THREADS;     // < 4096
                dst[idx] = (idx < 2048) ? srcH[idx] : srcM[idx - 2048];
            }
        }
        __syncthreads();

        const uint2* bptr = (const uint2*)(smem + SM_B) + l;
#pragma unroll 1
        for (int nbl = 0; nbl < 32; ++nbl) {
            const int c0 = tile * 256 + nbl * 8 + tg * 2;
            const float2 nn = *(const float2*)&snorm[c0];
            // 3 independent accumulator chains (breaks HMMA RAW chain)
            float hh[4] = {0.f, 0.f, 0.f, 0.f};
            float hm[4] = {0.f, 0.f, 0.f, 0.f};
            float mh[4] = {nn.x, nn.y, nn.x, nn.y};   // norm folded in
#pragma unroll
            for (int kb = 0; kb < 4; ++kb) {
                uint2 bh = bptr[(nbl * 4 + kb) * 32];
                uint2 bm = bptr[((32 + nbl) * 4 + kb) * 32];
                mma_bf16(hh, (const uint32_t*)&aH[kb], bh.x, bh.y);
                mma_bf16(hm, (const uint32_t*)&aH[kb], bm.x, bm.y);
                mma_bf16(mh, (const uint32_t*)&aM[kb], bh.x, bh.y);
            }
            const float d0 = hh[0] + hm[0] + mh[0];
            const float d1 = hh[1] + hm[1] + mh[1];
            const float d2 = hh[2] + hm[2] + mh[2];
            const float d3 = hh[3] + hm[3] + mh[3];
            // rare guard; sequential min updates minimize push counts
            if (fminf(d0, d1) < minv0 + MARGIN || fminf(d2, d3) < minv1 + MARGIN) {
                if (d0 < minv0 + MARGIN) {
                    int p = atomicAdd(&cnt[rL0], 1);
                    if (p < CAP) candI[rL0 * CAP + p] = (unsigned short)c0;
                }
                minv0 = fminf(minv0, d0);
                if (d1 < minv0 + MARGIN) {
                    int p = atomicAdd(&cnt[rL0], 1);
                    if (p < CAP) candI[rL0 * CAP + p] = (unsigned short)(c0 + 1);
                }
                minv0 = fminf(minv0, d1);
                if (d2 < minv1 + MARGIN) {
                    int p = atomicAdd(&cnt[rL1], 1);
                    if (p < CAP) candI[rL1 * CAP + p] = (unsigned short)c0;
                }
                minv1 = fminf(minv1, d2);
                if (d3 < minv1 + MARGIN) {
                    int p = atomicAdd(&cnt[rL1], 1);
                    if (p < CAP) candI[rL1 * CAP + p] = (unsigned short)(c0 + 1);
                }
                minv1 = fminf(minv1, d3);
            } else {
                minv0 = fminf(minv0, fminf(d0, d1));
                minv1 = fminf(minv1, fminf(d2, d3));
            }
        }
    }
    __syncthreads();

    // ---- exact refine + epilogue: one thread per row ----
    float* sLoss = (float*)(smem + SM_B);   // reuse B area
    if (t < M_TILE) {
        const int r = t;
        const float* xr = X + (size_t)(rowBase + r) * D_DIM;
        float bv = 3.4e38f;
        int bi = K_CODES;
        const int count = cnt[r];
        if (count > CAP) {
            // overflow fallback: exact scan over all codes (expected never at CAP=64)
            for (int c = 0; c < K_CODES; ++c) {
                const float* er = E + (size_t)c * D_DIM;
                float dot = 0.f;
#pragma unroll 16
                for (int dd = 0; dd < D_DIM; ++dd) dot = fmaf(xr[dd], er[dd], dot);
                float dv = fmaf(-2.f, dot, g_normE[c]);
                if (dv < bv) { bv = dv; bi = c; }
            }
        } else {
            // exact-recompute every pushed candidate (~25 typical)
            for (int i = 0; i < count; ++i) {
                int c = candI[r * CAP + i];
                const float* er = E + (size_t)c * D_DIM;
                float dot = 0.f;
#pragma unroll 16
                for (int dd = 0; dd < D_DIM; ++dd) dot = fmaf(xr[dd], er[dd], dot);
                float dv = fmaf(-2.f, dot, g_normE[c]);
                if (dv < bv || (dv == bv && c < bi)) { bv = dv; bi = c; }
            }
        }
        // gather codebook row, write quantized + index, accumulate loss
        const float4* erow = (const float4*)(E + (size_t)bi * D_DIM);
        const float4* xrow = (const float4*)xr;
        float* qout = out + (size_t)(rowBase + r) * D_DIM;
        float lsum = 0.f;
#pragma unroll
        for (int i = 0; i < D_DIM / 4; ++i) {
            float4 q = erow[i], x = xrow[i];
            float e0 = q.x - x.x, e1 = q.y - x.y, e2 = q.z - x.z, e3 = q.w - x.w;
            lsum += e0 * e0 + e1 * e1 + e2 * e2 + e3 * e3;
            *(float4*)(qout + i * 4) = q;
        }
        out[OUT_IDX + rowBase + r] = (float)bi;
        sLoss[r] = lsum;
    }
    __syncthreads();
    if (t < 64) sLoss[t] += sLoss[t + 64];
    __syncthreads();
    if (t < 32) sLoss[t] += sLoss[t + 32];
    __syncthreads();
    if (t == 0) {
        float s = 0.f;
#pragma unroll
        for (int i = 0; i < 32; ++i) s += sLoss[i];
        g_partials[blockIdx.x] = s;
    }
}

// ---------------------------------------------------------------------------
// Final loss:  loss = 1.25 * mean((q - x)^2), deterministic tree
// ---------------------------------------------------------------------------
__global__ void vq_loss_kernel(float* __restrict__ out) {
    __shared__ float sh[NUM_BLOCKS];
    int t = threadIdx.x;
    sh[t] = g_partials[t];
    __syncthreads();
    for (int s = NUM_BLOCKS / 2; s > 0; s >>= 1) {
        if (t < s) sh[t] += sh[t + s];
        __syncthreads();
    }
    if (t == 0) out[OUT_LOSS] = sh[0] * (1.25f / (float)(N_ROWS * D_DIM));
}

// ---------------------------------------------------------------------------
extern "C" void kernel_launch(void* const* d_in, const int* in_sizes, int n_in,
                              void* d_out, int out_size) {
    const float* X = (const float*)d_in[0];
    const float* E = (const float*)d_in[1];
    float* out = (float*)d_out;

    cudaFuncSetAttribute(vq_main_kernel,
                         cudaFuncAttributeMaxDynamicSharedMemorySize, SM_TOTAL);

    vq_prepA<<<(N_MB * 4 * 32 * 4 + 255) / 256, 256>>>(X);
    vq_prepB<<<(N_NB * 4 * 32 * 2 + 255) / 256, 256>>>(E);
    vq_norm_kernel<<<(K_CODES + 255) / 256, 256>>>(E);
    vq_main_kernel<<<NUM_BLOCKS, THREADS, SM_TOTAL>>>(X, E, out);
    vq_loss_kernel<<<1, NUM_BLOCKS>>>(out);
}

// round 10
// speedup vs baseline: 5.1430x; 5.1430x over previous
#include <cuda_runtime.h>
#include <cuda_bf16.h>
#include <cstdint>

// ---------------- problem constants ----------------
#define N_ROWS   65536
#define K_CODES  1024
#define D_DIM    64
#define M_TILE   128                    // rows per CTA
#define THREADS  256
#define NUM_BLOCKS (N_ROWS / M_TILE)    // 512
#define N_MB     (N_ROWS / 16)          // 4096 A row-blocks
#define N_NB     (K_CODES / 8)          // 128 B code-blocks
#define CAP      48
#define MARGIN   0.0625f

// Output layout (floats): [quantized 4194304][loss 1][indices 65536]
#define OUT_LOSS (N_ROWS * D_DIM)
#define OUT_IDX  (OUT_LOSS + 1)

// ---------------- device globals ----------------
// A fragments: [mb][kb][lane][reg] u32 (2 bf16 each), mma m16n8k16 order
__device__ uint32_t g_Ah[N_MB * 4 * 32 * 4];   // 8 MB
__device__ uint32_t g_Am[N_MB * 4 * 32 * 4];   // 8 MB
// B fragments: [nb][kb][lane][reg(2)] u32
__device__ uint32_t g_Bh[N_NB * 4 * 32 * 2];   // 128 KB
__device__ uint32_t g_Bm[N_NB * 4 * 32 * 2];   // 128 KB
__device__ float g_normE[K_CODES];
__device__ float g_partials[NUM_BLOCKS];

// ---------------- smem layout (bytes) ----------------
#define SM_B     0        // 65536: [plane(2)][nbl(32)][kb(4)][lane(32)][reg(2)] u32
#define SM_NORM  65536    // 4096: 1024 floats
#define SM_CANDV 69632    // 24576: 128 * CAP floats
#define SM_CANDI 94208    // 12288: 128 * CAP u16
#define SM_CNT   106496   // 512: 128 ints
#define SM_TOTAL 107008   // 104.5 KB -> 2 CTAs/SM (proven in R4)

// ---------------- helpers ----------------
__device__ __forceinline__ uint32_t pack_bf16(float lo, float hi) {
    __nv_bfloat16 a = __float2bfloat16(lo);
    __nv_bfloat16 b = __float2bfloat16(hi);
    uint16_t ua = *(uint16_t*)&a, ub = *(uint16_t*)&b;
    return (uint32_t)ua | ((uint32_t)ub << 16);
}
__device__ __forceinline__ float bf16val(float v) {
    __nv_bfloat16 b = __float2bfloat16(v);
    return __bfloat162float(b);
}
__device__ __forceinline__ void mma_bf16(float* c, const uint32_t* a,
                                         uint32_t b0, uint32_t b1) {
    asm volatile(
        "mma.sync.aligned.m16n8k16.row.col.f32.bf16.bf16.f32 "
        "{%0,%1,%2,%3}, {%4,%5,%6,%7}, {%8,%9}, {%0,%1,%2,%3};"
        : "+f"(c[0]), "+f"(c[1]), "+f"(c[2]), "+f"(c[3])
        : "r"(a[0]), "r"(a[1]), "r"(a[2]), "r"(a[3]), "r"(b0), "r"(b1));
}
// exact fp32 distance via float4 loads (coalesced-per-thread, 32 LDG.128 total)
__device__ __forceinline__ float exact_dist(const float4* xr4, const float* E,
                                            int c, float ne) {
    const float4* er4 = (const float4*)(E + (size_t)c * D_DIM);
    float dot = 0.f;
#pragma unroll
    for (int i = 0; i < D_DIM / 4; ++i) {
        float4 x = xr4[i], e = er4[i];
        dot = fmaf(x.x, e.x, dot); dot = fmaf(x.y, e.y, dot);
        dot = fmaf(x.z, e.z, dot); dot = fmaf(x.w, e.w, dot);
    }
    return fmaf(-2.f, dot, ne);
}

// ---------------------------------------------------------------------------
// Prep A: split (-2*X) into (hi, mid) bf16 planes, mma-fragment order
// ---------------------------------------------------------------------------
__global__ void vq_prepA(const float* __restrict__ X) {
    int tid = blockIdx.x * blockDim.x + threadIdx.x;
    if (tid >= N_MB * 4 * 32 * 4) return;
    int reg = tid & 3, lane = (tid >> 2) & 31, kb = (tid >> 7) & 3, mb = tid >> 9;
    int g = lane >> 2, tg = lane & 3;
    int row = mb * 16 + g + ((reg & 1) << 3);
    int col = kb * 16 + tg * 2 + ((reg & 2) << 2);
    const float* xp = X + (size_t)row * D_DIM + col;
    float v0 = -2.0f * xp[0], v1 = -2.0f * xp[1];
    float h0 = bf16val(v0), h1 = bf16val(v1);
    g_Ah[tid] = pack_bf16(v0, v1);
    g_Am[tid] = pack_bf16(v0 - h0, v1 - h1);
}

// ---------------------------------------------------------------------------
// Prep B: split E into (hi, mid) bf16 planes, mma-fragment order
// ---------------------------------------------------------------------------
__global__ void vq_prepB(const float* __restrict__ E) {
    int tid = blockIdx.x * blockDim.x + threadIdx.x;
    if (tid >= N_NB * 4 * 32 * 2) return;
    int reg = tid & 1, lane = (tid >> 1) & 31, kb = (tid >> 6) & 3, nb = tid >> 8;
    int g = lane >> 2, tg = lane & 3;
    int code = nb * 8 + g;
    int k = kb * 16 + tg * 2 + reg * 8;
    const float* ep = E + (size_t)code * D_DIM + k;
    float v0 = ep[0], v1 = ep[1];
    float h0 = bf16val(v0), h1 = bf16val(v1);
    g_Bh[tid] = pack_bf16(v0, v1);
    g_Bm[tid] = pack_bf16(v0 - h0, v1 - h1);
}

// ---------------------------------------------------------------------------
// Codebook norms
// ---------------------------------------------------------------------------
__global__ void vq_norm_kernel(const float* __restrict__ E) {
    int k = blockIdx.x * blockDim.x + threadIdx.x;
    if (k < K_CODES) {
        const float4* e = (const float4*)(E + (size_t)k * D_DIM);
        float s = 0.f;
#pragma unroll
        for (int i = 0; i < D_DIM / 4; ++i) {
            float4 v = e[i];
            s += v.x * v.x + v.y * v.y + v.z * v.z + v.w * v.w;
        }
        g_normE[k] = s;
    }
}

// ---------------------------------------------------------------------------
// Main: HMMA split distance GEMM (3 independent accumulator chains)
//       + margin-candidate list (values + indices) + value-pruned exact refine
// ---------------------------------------------------------------------------
__global__ __launch_bounds__(THREADS) void vq_main_kernel(
    const float* __restrict__ X, const float* __restrict__ E,
    float* __restrict__ out)
{
    extern __shared__ char smem[];
    float* snorm = (float*)(smem + SM_NORM);
    float* candV = (float*)(smem + SM_CANDV);
    unsigned short* candI = (unsigned short*)(smem + SM_CANDI);
    int* cnt = (int*)(smem + SM_CNT);

    const int t = threadIdx.x;
    const int w = t >> 5, l = t & 31;
    const int g = l >> 2, tg = l & 3;
    const int rowBase = blockIdx.x * M_TILE;

    if (t < M_TILE) cnt[t] = 0;
    for (int i = t; i < K_CODES; i += THREADS) snorm[i] = g_normE[i];

    // A fragments in registers for this warp's 16 rows
    const int mb = blockIdx.x * 8 + w;
    uint4 aH[4], aM[4];
#pragma unroll
    for (int kb = 0; kb < 4; ++kb) {
        aH[kb] = *(const uint4*)&g_Ah[((mb * 4 + kb) * 32 + l) * 4];
        aM[kb] = *(const uint4*)&g_Am[((mb * 4 + kb) * 32 + l) * 4];
    }

    float minv0 = 3.4e38f, minv1 = 3.4e38f;
    const int rL0 = w * 16 + g, rL1 = rL0 + 8;

#pragma unroll 1
    for (int tile = 0; tile < 4; ++tile) {
        __syncthreads();
        // stage B tile (32 nblocks, both planes) = 64KB
        {
            const uint4* srcH = (const uint4*)(g_Bh + tile * 8192);
            const uint4* srcM = (const uint4*)(g_Bm + tile * 8192);
            uint4* dst = (uint4*)(smem + SM_B);
#pragma unroll
            for (int i = 0; i < 16; ++i) {
                int idx = t + i * THREADS;     // < 4096
                dst[idx] = (idx < 2048) ? srcH[idx] : srcM[idx - 2048];
            }
        }
        __syncthreads();

        const uint2* bptr = (const uint2*)(smem + SM_B) + l;
#pragma unroll 1
        for (int nbl = 0; nbl < 32; ++nbl) {
            const int c0 = tile * 256 + nbl * 8 + tg * 2;
            const float2 nn = *(const float2*)&snorm[c0];
            // 3 independent accumulator chains (breaks HMMA RAW chain)
            float hh[4] = {0.f, 0.f, 0.f, 0.f};
            float hm[4] = {0.f, 0.f, 0.f, 0.f};
            float mh[4] = {nn.x, nn.y, nn.x, nn.y};   // norm folded in
#pragma unroll
            for (int kb = 0; kb < 4; ++kb) {
                uint2 bh = bptr[(nbl * 4 + kb) * 32];
                uint2 bm = bptr[((32 + nbl) * 4 + kb) * 32];
                mma_bf16(hh, (const uint32_t*)&aH[kb], bh.x, bh.y);
                mma_bf16(hm, (const uint32_t*)&aH[kb], bm.x, bm.y);
                mma_bf16(mh, (const uint32_t*)&aM[kb], bh.x, bh.y);
            }
            const float d0 = hh[0] + hm[0] + mh[0];
            const float d1 = hh[1] + hm[1] + mh[1];
            const float d2 = hh[2] + hm[2] + mh[2];
            const float d3 = hh[3] + hm[3] + mh[3];
            // rare guard; store approx value + index for later pruning
            if (fminf(d0, d1) < minv0 + MARGIN || fminf(d2, d3) < minv1 + MARGIN) {
                if (d0 < minv0 + MARGIN) {
                    int p = atomicAdd(&cnt[rL0], 1);
                    if (p < CAP) { candV[rL0 * CAP + p] = d0; candI[rL0 * CAP + p] = (unsigned short)c0; }
                }
                minv0 = fminf(minv0, d0);
                if (d1 < minv0 + MARGIN) {
                    int p = atomicAdd(&cnt[rL0], 1);
                    if (p < CAP) { candV[rL0 * CAP + p] = d1; candI[rL0 * CAP + p] = (unsigned short)(c0 + 1); }
                }
                minv0 = fminf(minv0, d1);
                if (d2 < minv1 + MARGIN) {
                    int p = atomicAdd(&cnt[rL1], 1);
                    if (p < CAP) { candV[rL1 * CAP + p] = d2; candI[rL1 * CAP + p] = (unsigned short)c0; }
                }
                minv1 = fminf(minv1, d2);
                if (d3 < minv1 + MARGIN) {
                    int p = atomicAdd(&cnt[rL1], 1);
                    if (p < CAP) { candV[rL1 * CAP + p] = d3; candI[rL1 * CAP + p] = (unsigned short)(c0 + 1); }
                }
                minv1 = fminf(minv1, d3);
            } else {
                minv0 = fminf(minv0, fminf(d0, d1));
                minv1 = fminf(minv1, fminf(d2, d3));
            }
        }
    }
    __syncthreads();

    // ---- value-pruned exact refine + epilogue: one thread per row ----
    float* sLoss = (float*)(smem + SM_B);   // reuse B area
    if (t < M_TILE) {
        const int r = t;
        const float4* xr4 = (const float4*)(X + (size_t)(rowBase + r) * D_DIM);
        float bv = 3.4e38f;
        int bi = K_CODES;
        const int count = cnt[r];
        if (count > CAP) {
            // overflow fallback: exact scan over all codes (rare)
            for (int c = 0; c < K_CODES; ++c) {
                float dv = exact_dist(xr4, E, c, g_normE[c]);
                if (dv < bv) { bv = dv; bi = c; }
            }
        } else {
            float mA = 3.4e38f;
            for (int i = 0; i < count; ++i)
                mA = fminf(mA, candV[r * CAP + i]);
            // exact-recompute only candidates within MARGIN of best approx (~1/row)
            for (int i = 0; i < count; ++i) {
                if (candV[r * CAP + i] > mA + MARGIN) continue;
                int c = candI[r * CAP + i];
                float dv = exact_dist(xr4, E, c, g_normE[c]);
                if (dv < bv || (dv == bv && c < bi)) { bv = dv; bi = c; }
            }
        }
        // gather codebook row, write quantized + index, accumulate loss
        const float4* erow = (const float4*)(E + (size_t)bi * D_DIM);
        float* qout = out + (size_t)(rowBase + r) * D_DIM;
        float lsum = 0.f;
#pragma unroll
        for (int i = 0; i < D_DIM / 4; ++i) {
            float4 q = erow[i], x = xr4[i];
            float e0 = q.x - x.x, e1 = q.y - x.y, e2 = q.z - x.z, e3 = q.w - x.w;
            lsum += e0 * e0 + e1 * e1 + e2 * e2 + e3 * e3;
            *(float4*)(qout + i * 4) = q;
        }
        out[OUT_IDX + rowBase + r] = (float)bi;
        sLoss[r] = lsum;
    }
    __syncthreads();
    if (t < 64) sLoss[t] += sLoss[t + 64];
    __syncthreads();
    if (t < 32) sLoss[t] += sLoss[t + 32];
    __syncthreads();
    if (t == 0) {
        float s = 0.f;
#pragma unroll
        for (int i = 0; i < 32; ++i) s += sLoss[i];
        g_partials[blockIdx.x] = s;
    }
}

// ---------------------------------------------------------------------------
// Final loss:  loss = 1.25 * mean((q - x)^2), deterministic tree
// ---------------------------------------------------------------------------
__global__ void vq_loss_kernel(float* __restrict__ out) {
    __shared__ float sh[NUM_BLOCKS];
    int t = threadIdx.x;
    sh[t] = g_partials[t];
    __syncthreads();
    for (int s = NUM_BLOCKS / 2; s > 0; s >>= 1) {
        if (t < s) sh[t] += sh[t + s];
        __syncthreads();
    }
    if (t == 0) out[OUT_LOSS] = sh[0] * (1.25f / (float)(N_ROWS * D_DIM));
}

// ---------------------------------------------------------------------------
extern "C" void kernel_launch(void* const* d_in, const int* in_sizes, int n_in,
                              void* d_out, int out_size) {
    const float* X = (const float*)d_in[0];
    const float* E = (const float*)d_in[1];
    float* out = (float*)d_out;

    cudaFuncSetAttribute(vq_main_kernel,
                         cudaFuncAttributeMaxDynamicSharedMemorySize, SM_TOTAL);

    vq_prepA<<<(N_MB * 4 * 32 * 4 + 255) / 256, 256>>>(X);
    vq_prepB<<<(N_NB * 4 * 32 * 2 + 255) / 256, 256>>>(E);
    vq_norm_kernel<<<(K_CODES + 255) / 256, 256>>>(E);
    vq_main_kernel<<<NUM_BLOCKS, THREADS, SM_TOTAL>>>(X, E, out);
    vq_loss_kernel<<<1, NUM_BLOCKS>>>(out);
}